// round 9
// baseline (speedup 1.0000x reference)
#include <cuda_runtime.h>
#include <math.h>

// Problem constants
#define B_      32
#define C_IN    8
#define C_OUT   16
#define H_      512
#define W_      512
#define KK      3
#define PLANES  (B_ * C_IN)            // 256
#define PLANE_ELEMS (H_ * W_)          // 262144
#define BPP     4                      // blocks per plane (R1 best-known geometry)
#define NBLOCKS (PLANES * BPP)         // 1024
#define NTHREADS 256
#define CHUNK_F8 (PLANE_ELEMS / 8 / BPP)  // 8192 f32x8 per block (32/thread)
#define AREA    264196.0f              // (H+K-1)^2 = 514^2

// Partial sums scratch: NBLOCKS floats, fully overwritten every launch.
__device__ float g_partial[NBLOCKS];

struct alignas(32) f32x8 { float v[8]; };

// 256-bit global load (sm_100+). Read-only path (.nc).
__device__ __forceinline__ f32x8 ldg256(const f32x8* __restrict__ p) {
    f32x8 r;
    asm volatile("ld.global.nc.v8.f32 {%0,%1,%2,%3,%4,%5,%6,%7}, [%8];"
                 : "=f"(r.v[0]), "=f"(r.v[1]), "=f"(r.v[2]), "=f"(r.v[3]),
                   "=f"(r.v[4]), "=f"(r.v[5]), "=f"(r.v[6]), "=f"(r.v[7])
                 : "l"(p));
    return r;
}

__global__ void __launch_bounds__(NTHREADS) reduce_planes_kernel(const f32x8* __restrict__ x) {
    const int blk   = blockIdx.x;
    const int plane = blk / BPP;
    const int sub   = blk % BPP;
    const f32x8* p  = x + (size_t)plane * (PLANE_ELEMS / 8) + (size_t)sub * CHUNK_F8;

    float s = 0.0f;
    // 8192 f32x8 / 256 threads = 32 per thread; unroll 4 -> 4 x 32B = 256B
    // in flight per thread (same outstanding bytes as R1's unroll-8 float4).
    #pragma unroll 4
    for (int i = threadIdx.x; i < CHUNK_F8; i += NTHREADS) {
        f32x8 a = ldg256(&p[i]);
        s += ((a.v[0] + a.v[1]) + (a.v[2] + a.v[3])) +
             ((a.v[4] + a.v[5]) + (a.v[6] + a.v[7]));
    }

    // warp reduce
    #pragma unroll
    for (int off = 16; off > 0; off >>= 1)
        s += __shfl_xor_sync(0xFFFFFFFFu, s, off);

    __shared__ float warp_sums[NTHREADS / 32];
    const int lane = threadIdx.x & 31;
    const int wid  = threadIdx.x >> 5;
    if (lane == 0) warp_sums[wid] = s;
    __syncthreads();

    if (wid == 0) {
        float t = (lane < NTHREADS / 32) ? warp_sums[lane] : 0.0f;
        #pragma unroll
        for (int off = 4; off > 0; off >>= 1)
            t += __shfl_xor_sync(0xFFFFFFFFu, t, off);
        if (lane == 0) g_partial[blk] = t;
    }
}

__global__ void __launch_bounds__(256) finalize_kernel(const float* __restrict__ w,
                                                       const float* __restrict__ bias,
                                                       float* __restrict__ out) {
    __shared__ float Sx[B_][C_IN];     // per-(n,ci) full plane sums
    __shared__ float Sw[C_OUT][C_IN];  // per-(co,ci) kernel-tap sums
    __shared__ float Sb[C_OUT];

    const int t = threadIdx.x;

    if (t < PLANES) {
        const float4 pv = *reinterpret_cast<const float4*>(&g_partial[t * BPP]);
        Sx[t / C_IN][t % C_IN] = (pv.x + pv.y) + (pv.z + pv.w);
    }
    if (t < C_OUT * C_IN) {
        const float* wp = w + t * (KK * KK);
        float ws = 0.0f;
        #pragma unroll
        for (int k = 0; k < KK * KK; k++) ws += wp[k];
        Sw[t / C_IN][t % C_IN] = ws;
    }
    if (t < C_OUT) Sb[t] = bias[t];
    __syncthreads();

    if (t < B_) {
        const float inv_area = 1.0f / AREA;
        float pooled[C_OUT];
        float mx = -INFINITY;
        #pragma unroll
        for (int co = 0; co < C_OUT; co++) {
            float d = 0.0f;
            #pragma unroll
            for (int ci = 0; ci < C_IN; ci++)
                d = fmaf(Sx[t][ci], Sw[co][ci], d);
            float v = d * inv_area + Sb[co];
            pooled[co] = v;
            mx = fmaxf(mx, v);
        }
        float se = 0.0f;
        #pragma unroll
        for (int co = 0; co < C_OUT; co++)
            se += __expf(pooled[co] - mx);
        out[t] = (mx + logf(se)) * 10.0f;
    }
}

extern "C" void kernel_launch(void* const* d_in, const int* in_sizes, int n_in,
                              void* d_out, int out_size) {
    const f32x8* x     = (const f32x8*)d_in[0];   // (32,8,512,512) fp32
    const float*  w    = (const float*)d_in[1];   // (16,8,3,3) fp32
    const float*  bias = (const float*)d_in[2];   // (16,1,1) fp32
    float* out = (float*)d_out;                   // (32,) fp32

    reduce_planes_kernel<<<NBLOCKS, NTHREADS>>>(x);
    finalize_kernel<<<1, 256>>>(w, bias, out);
}

// round 10
// speedup vs baseline: 1.0377x; 1.0377x over previous
#include <cuda_runtime.h>
#include <math.h>

// Problem constants
#define B_      32
#define C_IN    8
#define C_OUT   16
#define H_      512
#define W_      512
#define KK      3
#define PLANES  (B_ * C_IN)            // 256
#define PLANE_ELEMS (H_ * W_)          // 262144
#define BPP     4                      // blocks per plane (best-known geometry)
#define NWORK   (PLANES * BPP)         // 1024 worker blocks
#define NBLOCKS (NWORK + 1)            // +1 dedicated finalizer block
#define NTHREADS 256
#define CHUNK_F4 (PLANE_ELEMS / 4 / BPP)  // 16384 float4 per worker block
#define AREA    264196.0f              // (H+K-1)^2 = 514^2

// Scratch: g_partial fully overwritten every launch; g_count self-resets
// (finalizer writes 0 before exit) -> graph-replay safe.
__device__ __align__(16) float g_partial[NWORK];
__device__ unsigned int g_count = 0;

// Fire-and-forget release reduction: orders the prior g_partial store,
// no result wait, no MEMBAR on the exit path.
__device__ __forceinline__ void signal_done() {
    asm volatile("red.release.gpu.global.add.u32 [%0], 1;"
                 :: "l"(&g_count) : "memory");
}

__device__ __forceinline__ unsigned int poll_count() {
    unsigned int v;
    asm volatile("ld.acquire.gpu.global.u32 %0, [%1];"
                 : "=r"(v) : "l"(&g_count) : "memory");
    return v;
}

__global__ void __launch_bounds__(NTHREADS) fused_spin_kernel(const float4* __restrict__ x,
                                                              const float* __restrict__ w,
                                                              const float* __restrict__ bias,
                                                              float* __restrict__ out) {
    if (blockIdx.x != 0) {
        // ================= worker: R1 streaming reduce, verbatim =================
        const int blk   = blockIdx.x - 1;
        const int plane = blk / BPP;
        const int sub   = blk % BPP;
        const float4* p = x + (size_t)plane * (PLANE_ELEMS / 4) + (size_t)sub * CHUNK_F4;

        float s = 0.0f;
        // 16384 float4 / 256 threads = 64 per thread; batched loads -> high MLP.
        #pragma unroll 8
        for (int i = threadIdx.x; i < CHUNK_F4; i += NTHREADS) {
            float4 v = p[i];
            s += (v.x + v.y) + (v.z + v.w);
        }

        #pragma unroll
        for (int off = 16; off > 0; off >>= 1)
            s += __shfl_xor_sync(0xFFFFFFFFu, s, off);

        __shared__ float warp_sums[NTHREADS / 32];
        const int lane = threadIdx.x & 31;
        const int wid  = threadIdx.x >> 5;
        if (lane == 0) warp_sums[wid] = s;
        __syncthreads();

        if (wid == 0) {
            float t = (lane < NTHREADS / 32) ? warp_sums[lane] : 0.0f;
            #pragma unroll
            for (int off = 4; off > 0; off >>= 1)
                t += __shfl_xor_sync(0xFFFFFFFFu, t, off);
            if (lane == 0) {
                g_partial[blk] = t;
                signal_done();            // release-RED: store ordered, no wait
            }
        }
        return;
    }

    // ================= finalizer block (co-resident from t=0) =================
    const int t = threadIdx.x;

    // Preload weight sums / bias while workers stream (independent data).
    float ws = 0.0f;
    if (t < C_OUT * C_IN) {
        const float* wp = w + t * (KK * KK);
        #pragma unroll
        for (int k = 0; k < KK * KK; k++) ws += wp[k];
    }
    float bv = (t < C_OUT) ? bias[t] : 0.0f;

    // Wait for all 1024 worker signals (acquire -> partials visible).
    if (t == 0) {
        while (poll_count() != NWORK) __nanosleep(200);
        g_count = 0;                      // reset for next graph replay
    }
    __syncthreads();

    __shared__ float Sx[B_][C_IN];
    __shared__ float Sw[C_OUT][C_IN];
    __shared__ float Sb[C_OUT];

    if (t < PLANES) {
        const float4 pv = *reinterpret_cast<const float4*>(&g_partial[t * BPP]);
        Sx[t / C_IN][t % C_IN] = (pv.x + pv.y) + (pv.z + pv.w);
    }
    if (t < C_OUT * C_IN) Sw[t / C_IN][t % C_IN] = ws;
    if (t < C_OUT) Sb[t] = bv;
    __syncthreads();

    if (t < B_) {
        const float inv_area = 1.0f / AREA;
        float pooled[C_OUT];
        float mx = -INFINITY;
        #pragma unroll
        for (int co = 0; co < C_OUT; co++) {
            float d = 0.0f;
            #pragma unroll
            for (int ci = 0; ci < C_IN; ci++)
                d = fmaf(Sx[t][ci], Sw[co][ci], d);
            float v = d * inv_area + Sb[co];
            pooled[co] = v;
            mx = fmaxf(mx, v);
        }
        float se = 0.0f;
        #pragma unroll
        for (int co = 0; co < C_OUT; co++)
            se += __expf(pooled[co] - mx);
        out[t] = (mx + logf(se)) * 10.0f;
    }
}

extern "C" void kernel_launch(void* const* d_in, const int* in_sizes, int n_in,
                              void* d_out, int out_size) {
    const float4* x    = (const float4*)d_in[0];  // (32,8,512,512) fp32
    const float*  w    = (const float*)d_in[1];   // (16,8,3,3) fp32
    const float*  bias = (const float*)d_in[2];   // (16,1,1) fp32
    float* out = (float*)d_out;                   // (32,) fp32

    fused_spin_kernel<<<NBLOCKS, NTHREADS>>>(x, w, bias, out);
}